// round 14
// baseline (speedup 1.0000x reference)
#include <cuda_runtime.h>
#include <math.h>

// 64 threads/block, one sample. Memory plan (~20.2KB smem):
//  F[2048]: right envs; env of bond j at slot (j-1)*256, j=1..8 (16x16, stride 16)
//  M[1088]: raw absorbed middle tensor (16,16,4): [l*68 + r*4 + d]; site0/9 flat 64
//  A[1088]: arena.
//    Phase A: T (stride-68 env temp) = A[0..1087]; tb = A[320..575]
//    Phase B: m = A[0..319] (stride 20), W = A[320..575] (stride 16),
//             G = A[576..895] (col-major stride 20), sv = A[896..959]
//    Zip:     botS register dump = A[0..639]
//  Jacobi runs on warp 0 only (32-wide); all phase boundaries are __syncthreads.

struct SM {
    float F[2048];
    float M[1088];
    float A[1088];
    float small[640];
    float Eb[16], Eb2[16];
    float cn[16];
    float invn[4];
    float logn, logn2;
    int   kidx[4];
    int   xr[100];
};

__device__ __forceinline__ float wsum(float v) {
    #pragma unroll
    for (int o = 16; o > 0; o >>= 1) v += __shfl_xor_sync(0xffffffffu, v, o);
    return v;
}
__device__ __forceinline__ float wmax(float v) {
    #pragma unroll
    for (int o = 16; o > 0; o >>= 1) v = fmaxf(v, __shfl_xor_sync(0xffffffffu, v, o));
    return v;
}
__device__ __forceinline__ float d4(float4 a, float4 b) {
    return a.x * b.x + a.y * b.y + a.z * b.z + a.w * b.w;
}

// tb = A + 320 (256 floats), linear (v,w,il,ic)
__device__ __forceinline__ void stage(SM* s, const float* __restrict__ peps, int i, int j, int tid) {
    const float* base = peps + (size_t)(i * 10 + j) * 512;
    int xp = s->xr[i * 10 + j];
    float* tb = s->A + 320;
    #pragma unroll
    for (int t = 0; t < 4; t++) tb[tid + 64 * t] = base[(tid + 64 * t) * 2 + xp];
}

template<bool TOP>
__device__ __forceinline__ float tslice(SM* s, int v, int ph, int il, int ic) {
    int idx = TOP ? (((ph * 4 + v) * 4 + il) * 4 + ic)
                  : (((v * 4 + ph) * 4 + il) * 4 + ic);
    return s->A[320 + idx];
}

// 64-thread absorb: tid = (r = tid&15, a = tid>>4); rows l = 4a + il, il=0..3.
template<bool TOP>
__device__ void absorbM(SM* s, int j, int tid) {
    const float* sm = s->small + j * 64;
    int r = tid & 15, a = tid >> 4;
    int b = r >> 2, ic = r & 3;
    float4 mr = *(const float4*)(sm + (a * 4 + b) * 4);
    #pragma unroll
    for (int il = 0; il < 4; il++) {
        int l = 4 * a + il;
        float acc[4];
        #pragma unroll
        for (int ph = 0; ph < 4; ph++) {
            acc[ph] = mr.x * tslice<TOP>(s, 0, ph, il, ic)
                    + mr.y * tslice<TOP>(s, 1, ph, il, ic)
                    + mr.z * tslice<TOP>(s, 2, ph, il, ic)
                    + mr.w * tslice<TOP>(s, 3, ph, il, ic);
        }
        *(float4*)(s->M + l * 68 + r * 4) = make_float4(acc[0], acc[1], acc[2], acc[3]);
    }
}

template<bool TOP>
__device__ void absorb0(SM* s, int tid) {
    const float* sm = s->small;
    int e = tid;             // 64 elements exactly
    int ph = e & 3, r = e >> 2;
    int b = r >> 2, ic = r & 3;
    const float* mr = sm + b * 4;
    float acc = 0.f;
    #pragma unroll
    for (int v = 0; v < 4; v++) acc += mr[v] * tslice<TOP>(s, v, ph, 0, ic);
    s->M[e] = acc;  // [r*4+ph]
}

template<bool TOP>
__device__ void absorb9(SM* s, int tid) {
    const float* sm = s->small + 9 * 64;
    int e = tid;
    int ph = e & 3, l = e >> 2;
    int a = l >> 2, il = l & 3;
    const float* mr = sm + a * 4;
    float acc = 0.f;
    #pragma unroll
    for (int v = 0; v < 4; v++) acc += mr[v] * tslice<TOP>(s, v, ph, il, 0);
    s->M[e] = acc;  // [l*4+ph]
}

// env(bond j-1) = sum_d M_j env(bond j) M_j^T.
__device__ void envM(SM* s, int j, int tid) {
    const float* Fj = s->F + (j - 1) * 256;
    float* T = s->A;
    {
        int l = tid >> 2, d = tid & 3;     // 64 threads = one pass
        float Mr[16];
        #pragma unroll
        for (int r2 = 0; r2 < 16; r2++) Mr[r2] = s->M[l * 68 + r2 * 4 + d];
        float4 acc0 = make_float4(0.f, 0.f, 0.f, 0.f);
        float4 acc1 = make_float4(0.f, 0.f, 0.f, 0.f);
        float4 acc2 = make_float4(0.f, 0.f, 0.f, 0.f);
        float4 acc3 = make_float4(0.f, 0.f, 0.f, 0.f);
        #pragma unroll
        for (int r2 = 0; r2 < 16; r2++) {
            const float4* Fr = (const float4*)(Fj + r2 * 16);
            float mv = Mr[r2];
            float4 f0 = Fr[0], f1 = Fr[1], f2 = Fr[2], f3 = Fr[3];
            acc0.x += mv * f0.x; acc0.y += mv * f0.y; acc0.z += mv * f0.z; acc0.w += mv * f0.w;
            acc1.x += mv * f1.x; acc1.y += mv * f1.y; acc1.z += mv * f1.z; acc1.w += mv * f1.w;
            acc2.x += mv * f2.x; acc2.y += mv * f2.y; acc2.z += mv * f2.z; acc2.w += mv * f2.w;
            acc3.x += mv * f3.x; acc3.y += mv * f3.y; acc3.z += mv * f3.z; acc3.w += mv * f3.w;
        }
        T[l * 68 + 0 * 4 + d]  = acc0.x; T[l * 68 + 1 * 4 + d]  = acc0.y;
        T[l * 68 + 2 * 4 + d]  = acc0.z; T[l * 68 + 3 * 4 + d]  = acc0.w;
        T[l * 68 + 4 * 4 + d]  = acc1.x; T[l * 68 + 5 * 4 + d]  = acc1.y;
        T[l * 68 + 6 * 4 + d]  = acc1.z; T[l * 68 + 7 * 4 + d]  = acc1.w;
        T[l * 68 + 8 * 4 + d]  = acc2.x; T[l * 68 + 9 * 4 + d]  = acc2.y;
        T[l * 68 + 10 * 4 + d] = acc2.z; T[l * 68 + 11 * 4 + d] = acc2.w;
        T[l * 68 + 12 * 4 + d] = acc3.x; T[l * 68 + 13 * 4 + d] = acc3.y;
        T[l * 68 + 14 * 4 + d] = acc3.z; T[l * 68 + 15 * 4 + d] = acc3.w;
    }
    __syncthreads();
    float* Fn = s->F + (j - 2) * 256;
    {
        int l1 = tid >> 2, qd = tid & 3;   // 16 rows x 4 col-groups
        const float4* Ta = (const float4*)(T + l1 * 68);
        const float4* M0 = (const float4*)(s->M + (4 * qd + 0) * 68);
        const float4* M1 = (const float4*)(s->M + (4 * qd + 1) * 68);
        const float4* M2 = (const float4*)(s->M + (4 * qd + 2) * 68);
        const float4* M3 = (const float4*)(s->M + (4 * qd + 3) * 68);
        float a0 = 0.f, a1 = 0.f, a2 = 0.f, a3 = 0.f;
        #pragma unroll
        for (int q = 0; q < 16; q++) {
            float4 ta = Ta[q];
            a0 += d4(ta, M0[q]);
            a1 += d4(ta, M1[q]);
            a2 += d4(ta, M2[q]);
            a3 += d4(ta, M3[q]);
        }
        *(float4*)(Fn + l1 * 16 + 4 * qd) = make_float4(a0, a1, a2, a3);
    }
    __syncthreads();
}

__device__ __forceinline__ int pairP(int pr, int rnd) {
    return (pr == 0) ? 0 : ((pr - 1 + rnd) % 15) + 1;
}
__device__ __forceinline__ int pairQ(int pr, int rnd) {
    return ((14 - pr + rnd) % 15) + 1;
}

// One-sided Jacobi on G (col-major, stride 20, at A+576). WARP 0 ONLY.
__device__ void onesided16(SM* s, int lane) {
    int pr = lane >> 2, ql = lane & 3;
    float* Gc = s->A + 576;
    for (int sw = 0; sw < 6; sw++) {
        float mx = 0.f;
        for (int rnd = 0; rnd < 15; rnd++) {
            int p = pairP(pr, rnd), q = pairQ(pr, rnd);
            float4 gp = *(float4*)(Gc + p * 20 + ql * 4);
            float4 gq = *(float4*)(Gc + q * 20 + ql * 4);
            float dpp = gp.x * gp.x + gp.y * gp.y + gp.z * gp.z + gp.w * gp.w;
            float dqq = gq.x * gq.x + gq.y * gq.y + gq.z * gq.z + gq.w * gq.w;
            float dpq = gp.x * gq.x + gp.y * gq.y + gp.z * gq.z + gp.w * gq.w;
            dpp += __shfl_xor_sync(0xffffffffu, dpp, 1);
            dpp += __shfl_xor_sync(0xffffffffu, dpp, 2);
            dqq += __shfl_xor_sync(0xffffffffu, dqq, 1);
            dqq += __shfl_xor_sync(0xffffffffu, dqq, 2);
            dpq += __shfl_xor_sync(0xffffffffu, dpq, 1);
            dpq += __shfl_xor_sync(0xffffffffu, dpq, 2);
            float den = dpp * dqq;
            float r2 = dpq * dpq;
            mx = fmaxf(mx, r2 / fmaxf(den, 1e-45f));
            float c = 1.f, sn = 0.f;
            if (r2 > 1e-30f * den && r2 > 0.f) {
                float ta = (dqq - dpp) / (2.f * dpq);
                float tt = ((ta >= 0.f) ? 1.f : -1.f) / (fabsf(ta) + sqrtf(1.f + ta * ta));
                c = rsqrtf(1.f + tt * tt); sn = tt * c;
            }
            float4 np, nq;
            np.x = c * gp.x - sn * gq.x; nq.x = sn * gp.x + c * gq.x;
            np.y = c * gp.y - sn * gq.y; nq.y = sn * gp.y + c * gq.y;
            np.z = c * gp.z - sn * gq.z; nq.z = sn * gp.z + c * gq.z;
            np.w = c * gp.w - sn * gq.w; nq.w = sn * gp.w + c * gq.w;
            *(float4*)(Gc + p * 20 + ql * 4) = np;
            *(float4*)(Gc + q * 20 + ql * 4) = nq;
            __syncwarp();
        }
        if (sw >= 1) {
            mx = wmax(mx);
            if (mx < 1e-10f) break;
        }
    }
}

template<bool TOP>
__device__ void initRow(SM* s, const float* __restrict__ peps, int i, int tid) {
    for (int j = 0; j < 10; j++) {
        stage(s, peps, i, j, tid);
        __syncthreads();
        if (j == 9) {
            if (tid < 16) {
                int ph = tid & 3, il = tid >> 2;
                s->small[9 * 64 + tid] = tslice<TOP>(s, 0, ph, il, 0);
            }
        } else {
            int n = (j == 0) ? 16 : 64;
            if (tid < n) {
                int ph = tid & 3, ic = (tid >> 2) & 3, il = tid >> 4;
                s->small[j * 64 + tid] = tslice<TOP>(s, 0, ph, il, ic);
            }
        }
        __syncthreads();
    }
}

template<bool TOP>
__device__ void compress(SM* s, const float* __restrict__ peps, int i, int tid) {
    float* m  = s->A;          // stride 20
    float* W  = s->A + 320;    // stride 16
    float* G  = s->A + 576;    // col-major stride 20
    float* sv = s->A + 896;
    int lane = tid & 31, wid = tid >> 5;
    int rfix = tid & 15;
    int a4 = tid >> 4;         // 0..3
    // ---- Phase A: right environments ----
    stage(s, peps, i, 9, tid); __syncthreads();
    absorb9<TOP>(s, tid); __syncthreads();
    #pragma unroll
    for (int t = 0; t < 4; t++) {
        int e = tid + 64 * t; int l = e >> 4, l2 = e & 15;
        float acc = 0.f;
        #pragma unroll
        for (int d = 0; d < 4; d++) acc += s->M[l * 4 + d] * s->M[l2 * 4 + d];
        s->F[7 * 256 + e] = acc;   // env of bond 8 at slot 7
    }
    __syncthreads();
    for (int j = 8; j >= 2; j--) {
        stage(s, peps, i, j, tid); __syncthreads();
        absorbM<TOP>(s, j, tid); __syncthreads();
        envM(s, j, tid);
    }
    // ---- Phase B: left sweep ----
    stage(s, peps, i, 0, tid); __syncthreads();
    absorb0<TOP>(s, tid); __syncthreads();
    if (tid < 16) {
        int b = tid >> 2, d = tid & 3;
        s->small[b * 4 + d] = (b == d) ? 1.f : 0.f;   // site 0: keep-all, U = I gauge
    }
    if (tid < 32) {
        int r = tid & 15, dd = tid >> 4;
        sv[dd * 16 + r] = s->M[r * 4 + dd];
    }
    __syncthreads();
    for (int j = 1; j <= 8; j++) {
        stage(s, peps, i, j, tid); __syncthreads();
        absorbM<TOP>(s, j, tid); __syncthreads();
        // m[(a*4+d), r] = sum_b sv[a,b] M[b, r, d]: one a per thread
        {
            float4 acc = make_float4(0.f, 0.f, 0.f, 0.f);
            #pragma unroll
            for (int b = 0; b < 16; b++) {
                float4 Mb = *(const float4*)(s->M + b * 68 + rfix * 4);
                float s0 = sv[a4 * 16 + b];
                acc.x += s0 * Mb.x; acc.y += s0 * Mb.y; acc.z += s0 * Mb.z; acc.w += s0 * Mb.w;
            }
            m[(a4 * 4 + 0) * 20 + rfix] = acc.x;
            m[(a4 * 4 + 1) * 20 + rfix] = acc.y;
            m[(a4 * 4 + 2) * 20 + rfix] = acc.z;
            m[(a4 * 4 + 3) * 20 + rfix] = acc.w;
        }
        __syncthreads();
        // W = m * F[bond j]: cache this thread's F column (r = tid&15 invariant)
        {
            const float* Fj = s->F + (j - 1) * 256;
            float Fc[16];
            #pragma unroll
            for (int r2 = 0; r2 < 16; r2++) Fc[r2] = Fj[r2 * 16 + rfix];
            #pragma unroll
            for (int t = 0; t < 4; t++) {
                int rowp = a4 + 4 * t;
                const float4* mr = (const float4*)(m + rowp * 20);
                float4 m0 = mr[0], m1 = mr[1], m2 = mr[2], m3 = mr[3];
                float acc = m0.x * Fc[0] + m0.y * Fc[1] + m0.z * Fc[2] + m0.w * Fc[3]
                          + m1.x * Fc[4] + m1.y * Fc[5] + m1.z * Fc[6] + m1.w * Fc[7]
                          + m2.x * Fc[8] + m2.y * Fc[9] + m2.z * Fc[10] + m2.w * Fc[11]
                          + m3.x * Fc[12] + m3.y * Fc[13] + m3.z * Fc[14] + m3.w * Fc[15];
                W[rowp * 16 + rfix] = acc;
            }
        }
        __syncthreads();
        // G = W * m^T (col-major): cache this thread's m row
        {
            const float4* mr = (const float4*)(m + rfix * 20);
            float4 c0 = mr[0], c1 = mr[1], c2 = mr[2], c3 = mr[3];
            #pragma unroll
            for (int t = 0; t < 4; t++) {
                int rowp = a4 + 4 * t;
                const float4* Wp = (const float4*)(W + rowp * 16);
                float acc = d4(Wp[0], c0) + d4(Wp[1], c1) + d4(Wp[2], c2) + d4(Wp[3], c3);
                G[rfix * 20 + rowp] = acc;
            }
        }
        __syncthreads();
        if (wid == 0) onesided16(s, lane);
        __syncthreads();
        // column norms^2 = lambda^2
        if (tid < 16) {
            float n2 = 0.f;
            #pragma unroll
            for (int q = 0; q < 4; q++) {
                float4 g = *(float4*)(G + tid * 20 + q * 4);
                n2 += g.x * g.x + g.y * g.y + g.z * g.z + g.w * g.w;
            }
            s->cn[tid] = n2;
        }
        __syncthreads();
        if (tid == 0) {
            float dv[16];
            #pragma unroll
            for (int q = 0; q < 16; q++) dv[q] = s->cn[q];
            #pragma unroll
            for (int b = 0; b < 4; b++) {
                int bi = 0; float bv = dv[0];
                #pragma unroll
                for (int q = 1; q < 16; q++) if (dv[q] > bv) { bv = dv[q]; bi = q; }
                s->kidx[b] = bi; dv[bi] = -1.f;
                s->invn[b] = (bv > 1e-30f) ? rsqrtf(bv) : 0.f;
            }
        }
        __syncthreads();
        // small[j][(a*4+b)*4+d] = u_b[(a*4+d)] ; sv[b,r] = u_b^T m
        if (tid < 32) {
            int d = tid & 3, b = (tid >> 2) & 3, a = tid >> 4;
            s->small[j * 64 + tid] = G[s->kidx[b] * 20 + (a * 4 + d)] * s->invn[b];
            int r = tid & 15, b2 = tid >> 4;
            int ci = s->kidx[b2];
            float acc = 0.f;
            #pragma unroll
            for (int row = 0; row < 16; row++) acc += G[ci * 20 + row] * m[row * 20 + r];
            sv[tid] = acc * s->invn[b2];
        } else {
            int e = tid;  // tid 32..63 -> small elements 32..63
            int d = e & 3, b = (e >> 2) & 3, a = e >> 4;
            s->small[j * 64 + e] = G[s->kidx[b] * 20 + (a * 4 + d)] * s->invn[b];
            int r = e & 15, b2 = (e >> 4);  // b2 = 2,3
            int ci = s->kidx[b2];
            float acc = 0.f;
            #pragma unroll
            for (int row = 0; row < 16; row++) acc += G[ci * 20 + row] * m[row * 20 + r];
            sv[e] = acc * s->invn[b2];
        }
        __syncthreads();
    }
    // site 9
    stage(s, peps, i, 9, tid); __syncthreads();
    absorb9<TOP>(s, tid); __syncthreads();
    if (tid < 16) {
        int d = tid & 3, a = tid >> 2;
        float acc = 0.f;
        #pragma unroll
        for (int b = 0; b < 16; b++) acc += sv[a * 16 + b] * s->M[b * 4 + d];
        s->small[9 * 64 + tid] = acc;
    }
    __syncthreads();
    // ---- Phase C: normalize + logn, sites split across warps ----
    float lacc = 0.f;
    #pragma unroll
    for (int k = 0; k < 5; k++) {
        int js = wid * 5 + k;
        int n = (js == 0 || js == 9) ? 16 : 64;
        float ss = 0.f;
        for (int e = lane; e < n; e += 32) { float v = s->small[js * 64 + e]; ss += v * v; }
        ss = wsum(ss);
        float nrm = sqrtf(ss);
        float inv = (nrm > 1e-38f) ? (1.f / nrm) : 0.f;
        for (int e = lane; e < n; e += 32) s->small[js * 64 + e] *= inv;
        lacc += logf(fmaxf(nrm, 1e-38f));
    }
    if (lane == 0) {
        if (wid == 0) s->logn += lacc; else s->logn2 += lacc;
    }
    __syncthreads();
}

extern __shared__ float smraw[];

__global__ void __launch_bounds__(64, 8)
amp_kernel(const int* __restrict__ x, const float* __restrict__ peps, float* __restrict__ out) {
    SM* s = (SM*)smraw;
    int tid = threadIdx.x;
    int lane = tid & 31, wid = tid >> 5;
    int blk = blockIdx.x;
    for (int e = tid; e < 100; e += 64) s->xr[e] = x[blk * 100 + e];
    if (tid == 0) { s->logn = 0.f; s->logn2 = 0.f; }
    __syncthreads();

    initRow<false>(s, peps, 0, tid);
    for (int i = 1; i <= 4; i++) compress<false>(s, peps, i, tid);
    // bottom compressed MPS -> registers (10 per thread)
    float br[10];
    #pragma unroll
    for (int t = 0; t < 10; t++) br[t] = s->small[tid + 64 * t];
    __syncthreads();

    initRow<true>(s, peps, 9, tid);
    for (int i = 8; i >= 5; i--) compress<true>(s, peps, i, tid);

    // dump bottom MPS into the (dead) arena for the zip
    float* botS = s->A;
    #pragma unroll
    for (int t = 0; t < 10; t++) botS[tid + 64 * t] = br[t];
    __syncthreads();

    // ---- zip (warp 0 only) ----
    if (wid == 0) {
        if (lane < 16) {
            int c = lane >> 2, e2 = lane & 3;
            float acc = 0.f;
            #pragma unroll
            for (int d = 0; d < 4; d++) acc += botS[c * 4 + d] * s->small[e2 * 4 + d];
            s->Eb[lane] = acc;
        }
        __syncwarp();
        for (int j = 1; j <= 8; j++) {
            if (lane < 16) {
                int c = lane >> 2, e2 = lane & 3;
                float acc = 0.f;
                #pragma unroll
                for (int a = 0; a < 4; a++)
                    #pragma unroll
                    for (int b = 0; b < 4; b++) {
                        float ev = s->Eb[a * 4 + b];
                        float dot = 0.f;
                        #pragma unroll
                        for (int d = 0; d < 4; d++)
                            dot += botS[j * 64 + (a * 4 + c) * 4 + d]
                                 * s->small[j * 64 + (b * 4 + e2) * 4 + d];
                        acc += ev * dot;
                    }
                s->Eb2[lane] = acc;
            }
            __syncwarp();
            if (lane < 16) s->Eb[lane] = s->Eb2[lane];
            __syncwarp();
        }
        float part = 0.f;
        if (lane < 16) {
            int a = lane >> 2, b = lane & 3;
            float dot = 0.f;
            #pragma unroll
            for (int d = 0; d < 4; d++)
                dot += botS[9 * 64 + a * 4 + d] * s->small[9 * 64 + b * 4 + d];
            part = s->Eb[a * 4 + b] * dot;
        }
        part = wsum(part);
        if (lane == 0) out[blk] = part * expf(s->logn + s->logn2);
    }
}

extern "C" void kernel_launch(void* const* d_in, const int* in_sizes, int n_in,
                              void* d_out, int out_size) {
    const int* x;
    const float* peps;
    if (in_sizes[0] == 51200 && n_in >= 2) {
        peps = (const float*)d_in[0];
        x = (const int*)d_in[1];
    } else {
        x = (const int*)d_in[0];
        peps = (const float*)d_in[1];
    }
    float* out = (float*)d_out;
    cudaFuncSetAttribute(amp_kernel, cudaFuncAttributeMaxDynamicSharedMemorySize, (int)sizeof(SM));
    amp_kernel<<<out_size, 64, sizeof(SM)>>>(x, peps, out);
}

// round 15
// speedup vs baseline: 1.4907x; 1.4907x over previous
#include <cuda_runtime.h>
#include <math.h>

typedef unsigned long long ull;

// Memory plan (~20.2KB smem) — identical to R13:
//  F[2048]: right envs; env of bond j at slot (j-1)*256, j=1..8 (16x16, stride 16)
//  M[1088]: raw absorbed middle tensor (16,16,4): [l*68 + r*4 + d]; site0/9 flat 64
//  A[1088]: arena.
//    Phase A: T (stride-68 env temp) = A[0..1087]; tb = A[320..575]
//    Phase B: m = A[0..319] (stride 20), W = A[320..575] (stride 16),
//             G = A[576..895] (col-major stride 20), sv = A[896..959]
//    Zip:     botS register dump = A[0..639]

struct SM {
    float F[2048];
    float M[1088];
    float A[1088];
    float small[640];
    float Eb[16], Eb2[16];
    float cn[16];
    float invn[4];
    float logn;
    int   kidx[4];
    int   xr[100];
};

__device__ __forceinline__ float wsum(float v) {
    #pragma unroll
    for (int o = 16; o > 0; o >>= 1) v += __shfl_xor_sync(0xffffffffu, v, o);
    return v;
}
__device__ __forceinline__ float d4(float4 a, float4 b) {
    return a.x * b.x + a.y * b.y + a.z * b.z + a.w * b.w;
}

// tb = A + 320 (256 floats), linear (v,w,il,ic)
__device__ __forceinline__ void stage(SM* s, const float* __restrict__ peps, int i, int j, int lane) {
    const float* base = peps + (size_t)(i * 10 + j) * 512;
    int xp = s->xr[i * 10 + j];
    float* tb = s->A + 320;
    #pragma unroll
    for (int t = 0; t < 8; t++) tb[lane + 32 * t] = base[(lane + 32 * t) * 2 + xp];
}

template<bool TOP>
__device__ __forceinline__ float tslice(SM* s, int v, int ph, int il, int ic) {
    int idx = TOP ? (((ph * 4 + v) * 4 + il) * 4 + ic)
                  : (((v * 4 + ph) * 4 + il) * 4 + ic);
    return s->A[320 + idx];
}

// Register-tiled absorb: lane = (r = lane&15, hw = lane>>4); rows l = 8*hw + lt.
template<bool TOP>
__device__ void absorbM(SM* s, int j, int lane) {
    const float* sm = s->small + j * 64;
    int r = lane & 15, hw = lane >> 4;
    int b = r >> 2, ic = r & 3;
    float4 mr0 = *(const float4*)(sm + ((2 * hw) * 4 + b) * 4);
    float4 mr1 = *(const float4*)(sm + ((2 * hw + 1) * 4 + b) * 4);
    #pragma unroll
    for (int lt = 0; lt < 8; lt++) {
        int l = 8 * hw + lt;
        int il = lt & 3;
        float4 mr = (lt < 4) ? mr0 : mr1;
        float acc[4];
        #pragma unroll
        for (int ph = 0; ph < 4; ph++) {
            float a = mr.x * tslice<TOP>(s, 0, ph, il, ic)
                    + mr.y * tslice<TOP>(s, 1, ph, il, ic)
                    + mr.z * tslice<TOP>(s, 2, ph, il, ic)
                    + mr.w * tslice<TOP>(s, 3, ph, il, ic);
            acc[ph] = a;
        }
        *(float4*)(s->M + l * 68 + r * 4) = make_float4(acc[0], acc[1], acc[2], acc[3]);
    }
}

template<bool TOP>
__device__ void absorb0(SM* s, int lane) {
    const float* sm = s->small;
    #pragma unroll
    for (int t = 0; t < 2; t++) {
        int e = lane + 32 * t;
        int ph = e & 3, r = e >> 2;
        int b = r >> 2, ic = r & 3;
        const float* mr = sm + b * 4;
        float acc = 0.f;
        #pragma unroll
        for (int v = 0; v < 4; v++) acc += mr[v] * tslice<TOP>(s, v, ph, 0, ic);
        s->M[e] = acc;  // [r*4+ph]
    }
}

template<bool TOP>
__device__ void absorb9(SM* s, int lane) {
    const float* sm = s->small + 9 * 64;
    #pragma unroll
    for (int t = 0; t < 2; t++) {
        int e = lane + 32 * t;
        int ph = e & 3, l = e >> 2;
        int a = l >> 2, il = l & 3;
        const float* mr = sm + a * 4;
        float acc = 0.f;
        #pragma unroll
        for (int v = 0; v < 4; v++) acc += mr[v] * tslice<TOP>(s, v, ph, il, 0);
        s->M[e] = acc;  // [l*4+ph]
    }
}

// env(bond j-1) = sum_d M_j env(bond j) M_j^T.
__device__ void envM(SM* s, int j, int lane) {
    const float* Fj = s->F + (j - 1) * 256;
    float* T = s->A;
    #pragma unroll
    for (int g = 0; g < 2; g++) {
        int idx = lane + 32 * g;          // idx = 4*l + d
        int l = idx >> 2, d = idx & 3;
        float Mr[16];
        #pragma unroll
        for (int r2 = 0; r2 < 16; r2++) Mr[r2] = s->M[l * 68 + r2 * 4 + d];
        float4 acc0 = make_float4(0.f, 0.f, 0.f, 0.f);
        float4 acc1 = make_float4(0.f, 0.f, 0.f, 0.f);
        float4 acc2 = make_float4(0.f, 0.f, 0.f, 0.f);
        float4 acc3 = make_float4(0.f, 0.f, 0.f, 0.f);
        #pragma unroll
        for (int r2 = 0; r2 < 16; r2++) {
            const float4* Fr = (const float4*)(Fj + r2 * 16);
            float mv = Mr[r2];
            float4 f0 = Fr[0], f1 = Fr[1], f2 = Fr[2], f3 = Fr[3];
            acc0.x += mv * f0.x; acc0.y += mv * f0.y; acc0.z += mv * f0.z; acc0.w += mv * f0.w;
            acc1.x += mv * f1.x; acc1.y += mv * f1.y; acc1.z += mv * f1.z; acc1.w += mv * f1.w;
            acc2.x += mv * f2.x; acc2.y += mv * f2.y; acc2.z += mv * f2.z; acc2.w += mv * f2.w;
            acc3.x += mv * f3.x; acc3.y += mv * f3.y; acc3.z += mv * f3.z; acc3.w += mv * f3.w;
        }
        T[l * 68 + 0 * 4 + d]  = acc0.x; T[l * 68 + 1 * 4 + d]  = acc0.y;
        T[l * 68 + 2 * 4 + d]  = acc0.z; T[l * 68 + 3 * 4 + d]  = acc0.w;
        T[l * 68 + 4 * 4 + d]  = acc1.x; T[l * 68 + 5 * 4 + d]  = acc1.y;
        T[l * 68 + 6 * 4 + d]  = acc1.z; T[l * 68 + 7 * 4 + d]  = acc1.w;
        T[l * 68 + 8 * 4 + d]  = acc2.x; T[l * 68 + 9 * 4 + d]  = acc2.y;
        T[l * 68 + 10 * 4 + d] = acc2.z; T[l * 68 + 11 * 4 + d] = acc2.w;
        T[l * 68 + 12 * 4 + d] = acc3.x; T[l * 68 + 13 * 4 + d] = acc3.y;
        T[l * 68 + 14 * 4 + d] = acc3.z; T[l * 68 + 15 * 4 + d] = acc3.w;
    }
    __syncwarp();
    float* Fn = s->F + (j - 2) * 256;
    {
        int pr2 = lane >> 2, qd = lane & 3;
        int l1a = 2 * pr2;
        const float4* Ta = (const float4*)(T + l1a * 68);
        const float4* Tb = (const float4*)(T + (l1a + 1) * 68);
        const float4* M0 = (const float4*)(s->M + (4 * qd + 0) * 68);
        const float4* M1 = (const float4*)(s->M + (4 * qd + 1) * 68);
        const float4* M2 = (const float4*)(s->M + (4 * qd + 2) * 68);
        const float4* M3 = (const float4*)(s->M + (4 * qd + 3) * 68);
        float a0 = 0.f, a1 = 0.f, a2 = 0.f, a3 = 0.f;
        float b0 = 0.f, b1 = 0.f, b2 = 0.f, b3 = 0.f;
        #pragma unroll
        for (int q = 0; q < 16; q++) {
            float4 ta = Ta[q], tb = Tb[q];
            float4 m0 = M0[q]; a0 += d4(ta, m0); b0 += d4(tb, m0);
            float4 m1 = M1[q]; a1 += d4(ta, m1); b1 += d4(tb, m1);
            float4 m2 = M2[q]; a2 += d4(ta, m2); b2 += d4(tb, m2);
            float4 m3 = M3[q]; a3 += d4(ta, m3); b3 += d4(tb, m3);
        }
        *(float4*)(Fn + l1a * 16 + 4 * qd)       = make_float4(a0, a1, a2, a3);
        *(float4*)(Fn + (l1a + 1) * 16 + 4 * qd) = make_float4(b0, b1, b2, b3);
    }
    __syncwarp();
}

// One-sided Jacobi on G (col-major, stride 20, at A+576).
// Pair schedule from precomputed tables (4b x 15 rounds). Division-free exit
// test (flag |= r2 > 1e-9*den; __any_sync per sweep). Rotation + stores
// predicated on quad-uniform "needs rotation".
__device__ void onesided16(SM* s, int lane, ull pT, ull qT) {
    int ql = lane & 3;
    float* Gc = s->A + 576;
    for (int sw = 0; sw < 6; sw++) {
        int flag = 0;
        #pragma unroll
        for (int rnd = 0; rnd < 15; rnd++) {
            int p = (int)((pT >> (4 * rnd)) & 15ull);
            int q = (int)((qT >> (4 * rnd)) & 15ull);
            float4 gp = *(float4*)(Gc + p * 20 + ql * 4);
            float4 gq = *(float4*)(Gc + q * 20 + ql * 4);
            float dpp = gp.x * gp.x + gp.y * gp.y + gp.z * gp.z + gp.w * gp.w;
            float dqq = gq.x * gq.x + gq.y * gq.y + gq.z * gq.z + gq.w * gq.w;
            float dpq = gp.x * gq.x + gp.y * gq.y + gp.z * gq.z + gp.w * gq.w;
            dpp += __shfl_xor_sync(0xffffffffu, dpp, 1);
            dpp += __shfl_xor_sync(0xffffffffu, dpp, 2);
            dqq += __shfl_xor_sync(0xffffffffu, dqq, 1);
            dqq += __shfl_xor_sync(0xffffffffu, dqq, 2);
            dpq += __shfl_xor_sync(0xffffffffu, dpq, 1);
            dpq += __shfl_xor_sync(0xffffffffu, dpq, 2);
            float den = dpp * dqq;
            float r2 = dpq * dpq;
            flag |= (r2 > 1e-9f * den) ? 1 : 0;
            bool rot = (r2 > 1e-30f * den) && (r2 > 0.f);
            if (rot) {
                float ta = (dqq - dpp) / (2.f * dpq);
                float tt = ((ta >= 0.f) ? 1.f : -1.f) / (fabsf(ta) + sqrtf(1.f + ta * ta));
                float c = rsqrtf(1.f + tt * tt);
                float sn = tt * c;
                float4 np, nq;
                np.x = c * gp.x - sn * gq.x; nq.x = sn * gp.x + c * gq.x;
                np.y = c * gp.y - sn * gq.y; nq.y = sn * gp.y + c * gq.y;
                np.z = c * gp.z - sn * gq.z; nq.z = sn * gp.z + c * gq.z;
                np.w = c * gp.w - sn * gq.w; nq.w = sn * gp.w + c * gq.w;
                *(float4*)(Gc + p * 20 + ql * 4) = np;
                *(float4*)(Gc + q * 20 + ql * 4) = nq;
            }
            __syncwarp();
        }
        if (sw >= 1 && !__any_sync(0xffffffffu, flag)) break;
    }
}

template<bool TOP>
__device__ void initRow(SM* s, const float* __restrict__ peps, int i, int lane) {
    for (int j = 0; j < 10; j++) {
        stage(s, peps, i, j, lane);
        __syncwarp();
        if (j == 9) {
            if (lane < 16) {
                int ph = lane & 3, il = lane >> 2;
                s->small[9 * 64 + lane] = tslice<TOP>(s, 0, ph, il, 0);
            }
        } else {
            int n = (j == 0) ? 16 : 64;
            for (int e = lane; e < n; e += 32) {
                int ph = e & 3, ic = (e >> 2) & 3, il = e >> 4;
                s->small[j * 64 + e] = tslice<TOP>(s, 0, ph, il, ic);
            }
        }
        __syncwarp();
    }
}

template<bool TOP>
__device__ void compress(SM* s, const float* __restrict__ peps, int i, int lane, ull pT, ull qT) {
    float* m  = s->A;          // stride 20
    float* W  = s->A + 320;    // stride 16
    float* G  = s->A + 576;    // col-major stride 20
    float* sv = s->A + 896;
    int rfix = lane & 15;
    int hw = lane >> 4;
    // ---- Phase A: right environments ----
    stage(s, peps, i, 9, lane); __syncwarp();
    absorb9<TOP>(s, lane); __syncwarp();
    #pragma unroll
    for (int t = 0; t < 8; t++) {
        int e = lane + 32 * t; int l = e >> 4, l2 = e & 15;
        float acc = 0.f;
        #pragma unroll
        for (int d = 0; d < 4; d++) acc += s->M[l * 4 + d] * s->M[l2 * 4 + d];
        s->F[7 * 256 + e] = acc;   // env of bond 8 at slot 7
    }
    __syncwarp();
    for (int j = 8; j >= 2; j--) {
        stage(s, peps, i, j, lane); __syncwarp();
        absorbM<TOP>(s, j, lane); __syncwarp();
        envM(s, j, lane);
    }
    // ---- Phase B: left sweep ----
    stage(s, peps, i, 0, lane); __syncwarp();
    absorb0<TOP>(s, lane); __syncwarp();
    if (lane < 16) {
        int b = lane >> 2, d = lane & 3;
        s->small[b * 4 + d] = (b == d) ? 1.f : 0.f;   // site 0: keep-all, U = I gauge
    }
    #pragma unroll
    for (int t = 0; t < 2; t++) {
        int e = lane + 32 * t; int r = e & 15, dd = e >> 4;
        sv[dd * 16 + r] = s->M[r * 4 + dd];
    }
    __syncwarp();
    for (int j = 1; j <= 8; j++) {
        stage(s, peps, i, j, lane); __syncwarp();
        absorbM<TOP>(s, j, lane); __syncwarp();
        // m[(a*4+d), r] = sum_b sv[a,b] M[b, r, d] — float4 over d, shared M loads over a
        {
            float4 acc0 = make_float4(0.f, 0.f, 0.f, 0.f);
            float4 acc1 = make_float4(0.f, 0.f, 0.f, 0.f);
            int a0 = 2 * hw, a1 = 2 * hw + 1;
            #pragma unroll
            for (int b = 0; b < 16; b++) {
                float4 Mb = *(const float4*)(s->M + b * 68 + rfix * 4);
                float s0 = sv[a0 * 16 + b], s1 = sv[a1 * 16 + b];
                acc0.x += s0 * Mb.x; acc0.y += s0 * Mb.y; acc0.z += s0 * Mb.z; acc0.w += s0 * Mb.w;
                acc1.x += s1 * Mb.x; acc1.y += s1 * Mb.y; acc1.z += s1 * Mb.z; acc1.w += s1 * Mb.w;
            }
            m[(a0 * 4 + 0) * 20 + rfix] = acc0.x;
            m[(a0 * 4 + 1) * 20 + rfix] = acc0.y;
            m[(a0 * 4 + 2) * 20 + rfix] = acc0.z;
            m[(a0 * 4 + 3) * 20 + rfix] = acc0.w;
            m[(a1 * 4 + 0) * 20 + rfix] = acc1.x;
            m[(a1 * 4 + 1) * 20 + rfix] = acc1.y;
            m[(a1 * 4 + 2) * 20 + rfix] = acc1.z;
            m[(a1 * 4 + 3) * 20 + rfix] = acc1.w;
        }
        __syncwarp();
        // W = m * F[bond j]: cache this lane's F column (r = lane&15 invariant)
        {
            const float* Fj = s->F + (j - 1) * 256;
            float Fc[16];
            #pragma unroll
            for (int r2 = 0; r2 < 16; r2++) Fc[r2] = Fj[r2 * 16 + rfix];
            #pragma unroll
            for (int t = 0; t < 8; t++) {
                int rowp = hw + 2 * t;
                const float4* mr = (const float4*)(m + rowp * 20);
                float4 m0 = mr[0], m1 = mr[1], m2 = mr[2], m3 = mr[3];
                float acc = m0.x * Fc[0] + m0.y * Fc[1] + m0.z * Fc[2] + m0.w * Fc[3]
                          + m1.x * Fc[4] + m1.y * Fc[5] + m1.z * Fc[6] + m1.w * Fc[7]
                          + m2.x * Fc[8] + m2.y * Fc[9] + m2.z * Fc[10] + m2.w * Fc[11]
                          + m3.x * Fc[12] + m3.y * Fc[13] + m3.z * Fc[14] + m3.w * Fc[15];
                W[rowp * 16 + rfix] = acc;
            }
        }
        __syncwarp();
        // G = W * m^T (col-major): cache this lane's m row (row2 = lane&15 invariant)
        {
            const float4* mr = (const float4*)(m + rfix * 20);
            float4 c0 = mr[0], c1 = mr[1], c2 = mr[2], c3 = mr[3];
            #pragma unroll
            for (int t = 0; t < 8; t++) {
                int rowp = hw + 2 * t;
                const float4* Wp = (const float4*)(W + rowp * 16);
                float acc = d4(Wp[0], c0) + d4(Wp[1], c1) + d4(Wp[2], c2) + d4(Wp[3], c3);
                G[rfix * 20 + rowp] = acc;
            }
        }
        __syncwarp();
        onesided16(s, lane, pT, qT);
        // column norms^2 = lambda^2
        if (lane < 16) {
            float n2 = 0.f;
            #pragma unroll
            for (int q = 0; q < 4; q++) {
                float4 g = *(float4*)(G + lane * 20 + q * 4);
                n2 += g.x * g.x + g.y * g.y + g.z * g.z + g.w * g.w;
            }
            s->cn[lane] = n2;
        }
        __syncwarp();
        if (lane == 0) {
            float dv[16];
            #pragma unroll
            for (int q = 0; q < 16; q++) dv[q] = s->cn[q];
            #pragma unroll
            for (int b = 0; b < 4; b++) {
                int bi = 0; float bv = dv[0];
                #pragma unroll
                for (int q = 1; q < 16; q++) if (dv[q] > bv) { bv = dv[q]; bi = q; }
                s->kidx[b] = bi; dv[bi] = -1.f;
                s->invn[b] = (bv > 1e-30f) ? rsqrtf(bv) : 0.f;
            }
        }
        __syncwarp();
        // small[j][(a*4+b)*4+d] = u_b[(a*4+d)] = G[:,kidx[b]] * invn[b]
        #pragma unroll
        for (int t = 0; t < 2; t++) {
            int e = lane + 32 * t;
            int d = e & 3, b = (e >> 2) & 3, a = e >> 4;
            s->small[j * 64 + e] = G[s->kidx[b] * 20 + (a * 4 + d)] * s->invn[b];
        }
        // sv[b, r] = invn[b] * sum_row G[row, kidx[b]] m[row, r] = u_b^T m
        // (independent of the small-write above: reads G/m/invn, writes sv)
        #pragma unroll
        for (int t = 0; t < 2; t++) {
            int e = lane + 32 * t; int r = e & 15, b = e >> 4;
            int ci = s->kidx[b];
            float acc = 0.f;
            #pragma unroll
            for (int row = 0; row < 16; row++) acc += G[ci * 20 + row] * m[row * 20 + r];
            sv[e] = acc * s->invn[b];
        }
        __syncwarp();
    }
    // site 9
    stage(s, peps, i, 9, lane); __syncwarp();
    absorb9<TOP>(s, lane); __syncwarp();
    if (lane < 16) {
        int d = lane & 3, a = lane >> 2;
        float acc = 0.f;
        #pragma unroll
        for (int b = 0; b < 16; b++) acc += sv[a * 16 + b] * s->M[b * 4 + d];
        s->small[9 * 64 + lane] = acc;
    }
    __syncwarp();
    // ---- Phase C: normalize + logn (guarded) ----
    float lacc = 0.f;
    for (int js = 0; js < 10; js++) {
        int n = (js == 0 || js == 9) ? 16 : 64;
        float ss = 0.f;
        for (int e = lane; e < n; e += 32) { float v = s->small[js * 64 + e]; ss += v * v; }
        ss = wsum(ss);
        float nrm = sqrtf(ss);
        float inv = (nrm > 1e-38f) ? (1.f / nrm) : 0.f;
        for (int e = lane; e < n; e += 32) s->small[js * 64 + e] *= inv;
        lacc += logf(fmaxf(nrm, 1e-38f));
    }
    if (lane == 0) s->logn += lacc;
    __syncwarp();
}

extern __shared__ float smraw[];

__global__ void __launch_bounds__(32)
amp_kernel(const int* __restrict__ x, const float* __restrict__ peps, float* __restrict__ out) {
    SM* s = (SM*)smraw;
    int lane = threadIdx.x;
    int blk = blockIdx.x;
    for (int e = lane; e < 100; e += 32) s->xr[e] = x[blk * 100 + e];
    if (lane == 0) s->logn = 0.f;

    // Round-robin pair tables for this lane's pair index (lane>>2): 4 bits/round.
    int pr = lane >> 2;
    ull pT = 0, qT = 0;
    for (int rnd = 0; rnd < 15; rnd++) {
        int p = (pr == 0) ? 0 : ((pr - 1 + rnd) % 15) + 1;
        int q = ((14 - pr + rnd) % 15) + 1;
        pT |= ((ull)p) << (4 * rnd);
        qT |= ((ull)q) << (4 * rnd);
    }
    __syncwarp();

    initRow<false>(s, peps, 0, lane);
    for (int i = 1; i <= 4; i++) compress<false>(s, peps, i, lane, pT, qT);
    // bottom compressed MPS -> registers
    float br[20];
    #pragma unroll
    for (int t = 0; t < 20; t++) br[t] = s->small[lane + 32 * t];
    __syncwarp();

    initRow<true>(s, peps, 9, lane);
    for (int i = 8; i >= 5; i--) compress<true>(s, peps, i, lane, pT, qT);

    // dump bottom MPS into the (dead) arena for the zip
    float* botS = s->A;
    #pragma unroll
    for (int t = 0; t < 20; t++) botS[lane + 32 * t] = br[t];
    __syncwarp();

    // ---- zip ----
    if (lane < 16) {
        int c = lane >> 2, e2 = lane & 3;
        float acc = 0.f;
        #pragma unroll
        for (int d = 0; d < 4; d++) acc += botS[c * 4 + d] * s->small[e2 * 4 + d];
        s->Eb[lane] = acc;
    }
    __syncwarp();
    for (int j = 1; j <= 8; j++) {
        if (lane < 16) {
            int c = lane >> 2, e2 = lane & 3;
            float acc = 0.f;
            #pragma unroll
            for (int a = 0; a < 4; a++)
                #pragma unroll
                for (int b = 0; b < 4; b++) {
                    float ev = s->Eb[a * 4 + b];
                    float dot = 0.f;
                    #pragma unroll
                    for (int d = 0; d < 4; d++)
                        dot += botS[j * 64 + (a * 4 + c) * 4 + d]
                             * s->small[j * 64 + (b * 4 + e2) * 4 + d];
                    acc += ev * dot;
                }
            s->Eb2[lane] = acc;
        }
        __syncwarp();
        if (lane < 16) s->Eb[lane] = s->Eb2[lane];
        __syncwarp();
    }
    float part = 0.f;
    if (lane < 16) {
        int a = lane >> 2, b = lane & 3;
        float dot = 0.f;
        #pragma unroll
        for (int d = 0; d < 4; d++)
            dot += botS[9 * 64 + a * 4 + d] * s->small[9 * 64 + b * 4 + d];
        part = s->Eb[a * 4 + b] * dot;
    }
    part = wsum(part);
    if (lane == 0) out[blk] = part * expf(s->logn);
}

extern "C" void kernel_launch(void* const* d_in, const int* in_sizes, int n_in,
                              void* d_out, int out_size) {
    const int* x;
    const float* peps;
    if (in_sizes[0] == 51200 && n_in >= 2) {
        peps = (const float*)d_in[0];
        x = (const int*)d_in[1];
    } else {
        x = (const int*)d_in[0];
        peps = (const float*)d_in[1];
    }
    float* out = (float*)d_out;
    cudaFuncSetAttribute(amp_kernel, cudaFuncAttributeMaxDynamicSharedMemorySize, (int)sizeof(SM));
    amp_kernel<<<out_size, 32, sizeof(SM)>>>(x, peps, out);
}

// round 16
// speedup vs baseline: 1.6479x; 1.1055x over previous
#include <cuda_runtime.h>
#include <math.h>

typedef unsigned long long ull;

// Memory plan (~20.2KB smem) — identical to R15:
//  F[2048]: right envs; env of bond j at slot (j-1)*256, j=1..8 (16x16, stride 16)
//  M[1088]: raw absorbed middle tensor (16,16,4): [l*68 + r*4 + d]; site0/9 flat 64
//  A[1088]: arena.
//    Phase A: T (stride-68 env temp) = A[0..1087]; tb = A[320..575]
//    Phase B: m = A[0..319] (stride 20), W = A[320..575] (stride 16),
//             G = A[576..895] (col-major stride 20), sv = A[896..959]
//    Zip:     botS register dump = A[0..639]
//  peps loads are software-pipelined: ldg8 (gmem->regs, issued one site ahead)
//  + commit8 (regs->tb) so compute covers the ~240cyc L2 latency.

struct SM {
    float F[2048];
    float M[1088];
    float A[1088];
    float small[640];
    float Eb[16], Eb2[16];
    float cn[16];
    float invn[4];
    float logn;
    int   kidx[4];
    int   xr[100];
};

__device__ __forceinline__ float wsum(float v) {
    #pragma unroll
    for (int o = 16; o > 0; o >>= 1) v += __shfl_xor_sync(0xffffffffu, v, o);
    return v;
}
__device__ __forceinline__ float d4(float4 a, float4 b) {
    return a.x * b.x + a.y * b.y + a.z * b.z + a.w * b.w;
}

// Pipelined peps staging: site index is absolute (i*10+j).
__device__ __forceinline__ void ldg8(const float* __restrict__ peps, int site, int xp,
                                     float v[8], int lane) {
    const float* base = peps + (size_t)site * 512;
    #pragma unroll
    for (int t = 0; t < 8; t++) v[t] = base[(lane + 32 * t) * 2 + xp];
}
__device__ __forceinline__ void commit8(SM* s, const float v[8], int lane) {
    float* tb = s->A + 320;
    #pragma unroll
    for (int t = 0; t < 8; t++) tb[lane + 32 * t] = v[t];
}

template<bool TOP>
__device__ __forceinline__ float tslice(SM* s, int v, int ph, int il, int ic) {
    int idx = TOP ? (((ph * 4 + v) * 4 + il) * 4 + ic)
                  : (((v * 4 + ph) * 4 + il) * 4 + ic);
    return s->A[320 + idx];
}

// Register-tiled absorb: lane = (r = lane&15, hw = lane>>4); rows l = 8*hw + lt.
template<bool TOP>
__device__ void absorbM(SM* s, int j, int lane) {
    const float* sm = s->small + j * 64;
    int r = lane & 15, hw = lane >> 4;
    int b = r >> 2, ic = r & 3;
    float4 mr0 = *(const float4*)(sm + ((2 * hw) * 4 + b) * 4);
    float4 mr1 = *(const float4*)(sm + ((2 * hw + 1) * 4 + b) * 4);
    #pragma unroll
    for (int lt = 0; lt < 8; lt++) {
        int l = 8 * hw + lt;
        int il = lt & 3;
        float4 mr = (lt < 4) ? mr0 : mr1;
        float acc[4];
        #pragma unroll
        for (int ph = 0; ph < 4; ph++) {
            float a = mr.x * tslice<TOP>(s, 0, ph, il, ic)
                    + mr.y * tslice<TOP>(s, 1, ph, il, ic)
                    + mr.z * tslice<TOP>(s, 2, ph, il, ic)
                    + mr.w * tslice<TOP>(s, 3, ph, il, ic);
            acc[ph] = a;
        }
        *(float4*)(s->M + l * 68 + r * 4) = make_float4(acc[0], acc[1], acc[2], acc[3]);
    }
}

template<bool TOP>
__device__ void absorb0(SM* s, int lane) {
    const float* sm = s->small;
    #pragma unroll
    for (int t = 0; t < 2; t++) {
        int e = lane + 32 * t;
        int ph = e & 3, r = e >> 2;
        int b = r >> 2, ic = r & 3;
        const float* mr = sm + b * 4;
        float acc = 0.f;
        #pragma unroll
        for (int v = 0; v < 4; v++) acc += mr[v] * tslice<TOP>(s, v, ph, 0, ic);
        s->M[e] = acc;  // [r*4+ph]
    }
}

template<bool TOP>
__device__ void absorb9(SM* s, int lane) {
    const float* sm = s->small + 9 * 64;
    #pragma unroll
    for (int t = 0; t < 2; t++) {
        int e = lane + 32 * t;
        int ph = e & 3, l = e >> 2;
        int a = l >> 2, il = l & 3;
        const float* mr = sm + a * 4;
        float acc = 0.f;
        #pragma unroll
        for (int v = 0; v < 4; v++) acc += mr[v] * tslice<TOP>(s, v, ph, il, 0);
        s->M[e] = acc;  // [l*4+ph]
    }
}

// env(bond j-1) = sum_d M_j env(bond j) M_j^T.
__device__ void envM(SM* s, int j, int lane) {
    const float* Fj = s->F + (j - 1) * 256;
    float* T = s->A;
    #pragma unroll
    for (int g = 0; g < 2; g++) {
        int idx = lane + 32 * g;          // idx = 4*l + d
        int l = idx >> 2, d = idx & 3;
        float Mr[16];
        #pragma unroll
        for (int r2 = 0; r2 < 16; r2++) Mr[r2] = s->M[l * 68 + r2 * 4 + d];
        float4 acc0 = make_float4(0.f, 0.f, 0.f, 0.f);
        float4 acc1 = make_float4(0.f, 0.f, 0.f, 0.f);
        float4 acc2 = make_float4(0.f, 0.f, 0.f, 0.f);
        float4 acc3 = make_float4(0.f, 0.f, 0.f, 0.f);
        #pragma unroll
        for (int r2 = 0; r2 < 16; r2++) {
            const float4* Fr = (const float4*)(Fj + r2 * 16);
            float mv = Mr[r2];
            float4 f0 = Fr[0], f1 = Fr[1], f2 = Fr[2], f3 = Fr[3];
            acc0.x += mv * f0.x; acc0.y += mv * f0.y; acc0.z += mv * f0.z; acc0.w += mv * f0.w;
            acc1.x += mv * f1.x; acc1.y += mv * f1.y; acc1.z += mv * f1.z; acc1.w += mv * f1.w;
            acc2.x += mv * f2.x; acc2.y += mv * f2.y; acc2.z += mv * f2.z; acc2.w += mv * f2.w;
            acc3.x += mv * f3.x; acc3.y += mv * f3.y; acc3.z += mv * f3.z; acc3.w += mv * f3.w;
        }
        T[l * 68 + 0 * 4 + d]  = acc0.x; T[l * 68 + 1 * 4 + d]  = acc0.y;
        T[l * 68 + 2 * 4 + d]  = acc0.z; T[l * 68 + 3 * 4 + d]  = acc0.w;
        T[l * 68 + 4 * 4 + d]  = acc1.x; T[l * 68 + 5 * 4 + d]  = acc1.y;
        T[l * 68 + 6 * 4 + d]  = acc1.z; T[l * 68 + 7 * 4 + d]  = acc1.w;
        T[l * 68 + 8 * 4 + d]  = acc2.x; T[l * 68 + 9 * 4 + d]  = acc2.y;
        T[l * 68 + 10 * 4 + d] = acc2.z; T[l * 68 + 11 * 4 + d] = acc2.w;
        T[l * 68 + 12 * 4 + d] = acc3.x; T[l * 68 + 13 * 4 + d] = acc3.y;
        T[l * 68 + 14 * 4 + d] = acc3.z; T[l * 68 + 15 * 4 + d] = acc3.w;
    }
    __syncwarp();
    float* Fn = s->F + (j - 2) * 256;
    {
        int pr2 = lane >> 2, qd = lane & 3;
        int l1a = 2 * pr2;
        const float4* Ta = (const float4*)(T + l1a * 68);
        const float4* Tb = (const float4*)(T + (l1a + 1) * 68);
        const float4* M0 = (const float4*)(s->M + (4 * qd + 0) * 68);
        const float4* M1 = (const float4*)(s->M + (4 * qd + 1) * 68);
        const float4* M2 = (const float4*)(s->M + (4 * qd + 2) * 68);
        const float4* M3 = (const float4*)(s->M + (4 * qd + 3) * 68);
        float a0 = 0.f, a1 = 0.f, a2 = 0.f, a3 = 0.f;
        float b0 = 0.f, b1 = 0.f, b2 = 0.f, b3 = 0.f;
        #pragma unroll
        for (int q = 0; q < 16; q++) {
            float4 ta = Ta[q], tb = Tb[q];
            float4 m0 = M0[q]; a0 += d4(ta, m0); b0 += d4(tb, m0);
            float4 m1 = M1[q]; a1 += d4(ta, m1); b1 += d4(tb, m1);
            float4 m2 = M2[q]; a2 += d4(ta, m2); b2 += d4(tb, m2);
            float4 m3 = M3[q]; a3 += d4(ta, m3); b3 += d4(tb, m3);
        }
        *(float4*)(Fn + l1a * 16 + 4 * qd)       = make_float4(a0, a1, a2, a3);
        *(float4*)(Fn + (l1a + 1) * 16 + 4 * qd) = make_float4(b0, b1, b2, b3);
    }
    __syncwarp();
}

// One-sided Jacobi on G (col-major, stride 20, at A+576).
__device__ void onesided16(SM* s, int lane, ull pT, ull qT) {
    int ql = lane & 3;
    float* Gc = s->A + 576;
    for (int sw = 0; sw < 6; sw++) {
        int flag = 0;
        #pragma unroll
        for (int rnd = 0; rnd < 15; rnd++) {
            int p = (int)((pT >> (4 * rnd)) & 15ull);
            int q = (int)((qT >> (4 * rnd)) & 15ull);
            float4 gp = *(float4*)(Gc + p * 20 + ql * 4);
            float4 gq = *(float4*)(Gc + q * 20 + ql * 4);
            float dpp = gp.x * gp.x + gp.y * gp.y + gp.z * gp.z + gp.w * gp.w;
            float dqq = gq.x * gq.x + gq.y * gq.y + gq.z * gq.z + gq.w * gq.w;
            float dpq = gp.x * gq.x + gp.y * gq.y + gp.z * gq.z + gp.w * gq.w;
            dpp += __shfl_xor_sync(0xffffffffu, dpp, 1);
            dpp += __shfl_xor_sync(0xffffffffu, dpp, 2);
            dqq += __shfl_xor_sync(0xffffffffu, dqq, 1);
            dqq += __shfl_xor_sync(0xffffffffu, dqq, 2);
            dpq += __shfl_xor_sync(0xffffffffu, dpq, 1);
            dpq += __shfl_xor_sync(0xffffffffu, dpq, 2);
            float den = dpp * dqq;
            float r2 = dpq * dpq;
            flag |= (r2 > 1e-9f * den) ? 1 : 0;
            bool rot = (r2 > 1e-30f * den) && (r2 > 0.f);
            if (rot) {
                float ta = (dqq - dpp) / (2.f * dpq);
                float tt = ((ta >= 0.f) ? 1.f : -1.f) / (fabsf(ta) + sqrtf(1.f + ta * ta));
                float c = rsqrtf(1.f + tt * tt);
                float sn = tt * c;
                float4 np, nq;
                np.x = c * gp.x - sn * gq.x; nq.x = sn * gp.x + c * gq.x;
                np.y = c * gp.y - sn * gq.y; nq.y = sn * gp.y + c * gq.y;
                np.z = c * gp.z - sn * gq.z; nq.z = sn * gp.z + c * gq.z;
                np.w = c * gp.w - sn * gq.w; nq.w = sn * gp.w + c * gq.w;
                *(float4*)(Gc + p * 20 + ql * 4) = np;
                *(float4*)(Gc + q * 20 + ql * 4) = nq;
            }
            __syncwarp();
        }
        if (sw >= 1 && !__any_sync(0xffffffffu, flag)) break;
    }
}

template<bool TOP>
__device__ void initRow(SM* s, const float* __restrict__ peps, int i, int lane) {
    float v[8];
    ldg8(peps, i * 10 + 0, s->xr[i * 10 + 0], v, lane);
    for (int j = 0; j < 10; j++) {
        commit8(s, v, lane);
        __syncwarp();
        if (j < 9) ldg8(peps, i * 10 + j + 1, s->xr[i * 10 + j + 1], v, lane);
        if (j == 9) {
            if (lane < 16) {
                int ph = lane & 3, il = lane >> 2;
                s->small[9 * 64 + lane] = tslice<TOP>(s, 0, ph, il, 0);
            }
        } else {
            int n = (j == 0) ? 16 : 64;
            for (int e = lane; e < n; e += 32) {
                int ph = e & 3, ic = (e >> 2) & 3, il = e >> 4;
                s->small[j * 64 + e] = tslice<TOP>(s, 0, ph, il, ic);
            }
        }
        __syncwarp();
    }
}

template<bool TOP>
__device__ void compress(SM* s, const float* __restrict__ peps, int i, int lane, ull pT, ull qT) {
    float* m  = s->A;          // stride 20
    float* W  = s->A + 320;    // stride 16
    float* G  = s->A + 576;    // col-major stride 20
    float* sv = s->A + 896;
    int rfix = lane & 15;
    int hw = lane >> 4;
    int b10 = i * 10;
    float v[8];
    // ---- Phase A: right environments ----
    ldg8(peps, b10 + 9, s->xr[b10 + 9], v, lane);
    commit8(s, v, lane); __syncwarp();
    ldg8(peps, b10 + 8, s->xr[b10 + 8], v, lane);   // prefetch site 8
    absorb9<TOP>(s, lane); __syncwarp();
    #pragma unroll
    for (int t = 0; t < 8; t++) {
        int e = lane + 32 * t; int l = e >> 4, l2 = e & 15;
        float acc = 0.f;
        #pragma unroll
        for (int d = 0; d < 4; d++) acc += s->M[l * 4 + d] * s->M[l2 * 4 + d];
        s->F[7 * 256 + e] = acc;   // env of bond 8 at slot 7
    }
    __syncwarp();
    for (int j = 8; j >= 2; j--) {
        commit8(s, v, lane); __syncwarp();
        int nj = (j > 2) ? (j - 1) : 0;           // after j==2 comes Phase-B site 0
        ldg8(peps, b10 + nj, s->xr[b10 + nj], v, lane);
        absorbM<TOP>(s, j, lane); __syncwarp();
        envM(s, j, lane);
    }
    // ---- Phase B: left sweep ----
    commit8(s, v, lane); __syncwarp();            // site 0
    ldg8(peps, b10 + 1, s->xr[b10 + 1], v, lane);
    absorb0<TOP>(s, lane); __syncwarp();
    if (lane < 16) {
        int b = lane >> 2, d = lane & 3;
        s->small[b * 4 + d] = (b == d) ? 1.f : 0.f;   // site 0: keep-all, U = I gauge
    }
    #pragma unroll
    for (int t = 0; t < 2; t++) {
        int e = lane + 32 * t; int r = e & 15, dd = e >> 4;
        sv[dd * 16 + r] = s->M[r * 4 + dd];
    }
    __syncwarp();
    for (int j = 1; j <= 8; j++) {
        commit8(s, v, lane); __syncwarp();
        int nj = (j < 8) ? (j + 1) : 9;
        ldg8(peps, b10 + nj, s->xr[b10 + nj], v, lane);
        absorbM<TOP>(s, j, lane); __syncwarp();
        // m[(a*4+d), r] = sum_b sv[a,b] M[b, r, d]
        {
            float4 acc0 = make_float4(0.f, 0.f, 0.f, 0.f);
            float4 acc1 = make_float4(0.f, 0.f, 0.f, 0.f);
            int a0 = 2 * hw, a1 = 2 * hw + 1;
            #pragma unroll
            for (int b = 0; b < 16; b++) {
                float4 Mb = *(const float4*)(s->M + b * 68 + rfix * 4);
                float s0 = sv[a0 * 16 + b], s1 = sv[a1 * 16 + b];
                acc0.x += s0 * Mb.x; acc0.y += s0 * Mb.y; acc0.z += s0 * Mb.z; acc0.w += s0 * Mb.w;
                acc1.x += s1 * Mb.x; acc1.y += s1 * Mb.y; acc1.z += s1 * Mb.z; acc1.w += s1 * Mb.w;
            }
            m[(a0 * 4 + 0) * 20 + rfix] = acc0.x;
            m[(a0 * 4 + 1) * 20 + rfix] = acc0.y;
            m[(a0 * 4 + 2) * 20 + rfix] = acc0.z;
            m[(a0 * 4 + 3) * 20 + rfix] = acc0.w;
            m[(a1 * 4 + 0) * 20 + rfix] = acc1.x;
            m[(a1 * 4 + 1) * 20 + rfix] = acc1.y;
            m[(a1 * 4 + 2) * 20 + rfix] = acc1.z;
            m[(a1 * 4 + 3) * 20 + rfix] = acc1.w;
        }
        __syncwarp();
        // W = m * F[bond j]
        {
            const float* Fj = s->F + (j - 1) * 256;
            float Fc[16];
            #pragma unroll
            for (int r2 = 0; r2 < 16; r2++) Fc[r2] = Fj[r2 * 16 + rfix];
            #pragma unroll
            for (int t = 0; t < 8; t++) {
                int rowp = hw + 2 * t;
                const float4* mr = (const float4*)(m + rowp * 20);
                float4 m0 = mr[0], m1 = mr[1], m2 = mr[2], m3 = mr[3];
                float acc = m0.x * Fc[0] + m0.y * Fc[1] + m0.z * Fc[2] + m0.w * Fc[3]
                          + m1.x * Fc[4] + m1.y * Fc[5] + m1.z * Fc[6] + m1.w * Fc[7]
                          + m2.x * Fc[8] + m2.y * Fc[9] + m2.z * Fc[10] + m2.w * Fc[11]
                          + m3.x * Fc[12] + m3.y * Fc[13] + m3.z * Fc[14] + m3.w * Fc[15];
                W[rowp * 16 + rfix] = acc;
            }
        }
        __syncwarp();
        // G = W * m^T (col-major)
        {
            const float4* mr = (const float4*)(m + rfix * 20);
            float4 c0 = mr[0], c1 = mr[1], c2 = mr[2], c3 = mr[3];
            #pragma unroll
            for (int t = 0; t < 8; t++) {
                int rowp = hw + 2 * t;
                const float4* Wp = (const float4*)(W + rowp * 16);
                float acc = d4(Wp[0], c0) + d4(Wp[1], c1) + d4(Wp[2], c2) + d4(Wp[3], c3);
                G[rfix * 20 + rowp] = acc;
            }
        }
        __syncwarp();
        onesided16(s, lane, pT, qT);
        // column norms^2 = lambda^2
        if (lane < 16) {
            float n2 = 0.f;
            #pragma unroll
            for (int q = 0; q < 4; q++) {
                float4 g = *(float4*)(G + lane * 20 + q * 4);
                n2 += g.x * g.x + g.y * g.y + g.z * g.z + g.w * g.w;
            }
            s->cn[lane] = n2;
        }
        __syncwarp();
        if (lane == 0) {
            float dv[16];
            #pragma unroll
            for (int q = 0; q < 16; q++) dv[q] = s->cn[q];
            #pragma unroll
            for (int b = 0; b < 4; b++) {
                int bi = 0; float bv = dv[0];
                #pragma unroll
                for (int q = 1; q < 16; q++) if (dv[q] > bv) { bv = dv[q]; bi = q; }
                s->kidx[b] = bi; dv[bi] = -1.f;
                s->invn[b] = (bv > 1e-30f) ? rsqrtf(bv) : 0.f;
            }
        }
        __syncwarp();
        // small[j][(a*4+b)*4+d] = u_b[(a*4+d)] = G[:,kidx[b]] * invn[b]
        #pragma unroll
        for (int t = 0; t < 2; t++) {
            int e = lane + 32 * t;
            int d = e & 3, b = (e >> 2) & 3, a = e >> 4;
            s->small[j * 64 + e] = G[s->kidx[b] * 20 + (a * 4 + d)] * s->invn[b];
        }
        // sv[b, r] = invn[b] * sum_row G[row, kidx[b]] m[row, r] = u_b^T m
        #pragma unroll
        for (int t = 0; t < 2; t++) {
            int e = lane + 32 * t; int r = e & 15, b = e >> 4;
            int ci = s->kidx[b];
            float acc = 0.f;
            #pragma unroll
            for (int row = 0; row < 16; row++) acc += G[ci * 20 + row] * m[row * 20 + r];
            sv[e] = acc * s->invn[b];
        }
        __syncwarp();
    }
    // site 9
    commit8(s, v, lane); __syncwarp();
    absorb9<TOP>(s, lane); __syncwarp();
    if (lane < 16) {
        int d = lane & 3, a = lane >> 2;
        float acc = 0.f;
        #pragma unroll
        for (int b = 0; b < 16; b++) acc += sv[a * 16 + b] * s->M[b * 4 + d];
        s->small[9 * 64 + lane] = acc;
    }
    __syncwarp();
    // ---- Phase C: normalize + logn (guarded) ----
    float lacc = 0.f;
    for (int js = 0; js < 10; js++) {
        int n = (js == 0 || js == 9) ? 16 : 64;
        float ss = 0.f;
        for (int e = lane; e < n; e += 32) { float w = s->small[js * 64 + e]; ss += w * w; }
        ss = wsum(ss);
        float nrm = sqrtf(ss);
        float inv = (nrm > 1e-38f) ? (1.f / nrm) : 0.f;
        for (int e = lane; e < n; e += 32) s->small[js * 64 + e] *= inv;
        lacc += logf(fmaxf(nrm, 1e-38f));
    }
    if (lane == 0) s->logn += lacc;
    __syncwarp();
}

extern __shared__ float smraw[];

__global__ void __launch_bounds__(32)
amp_kernel(const int* __restrict__ x, const float* __restrict__ peps, float* __restrict__ out) {
    SM* s = (SM*)smraw;
    int lane = threadIdx.x;
    int blk = blockIdx.x;
    for (int e = lane; e < 100; e += 32) s->xr[e] = x[blk * 100 + e];
    if (lane == 0) s->logn = 0.f;

    // Round-robin pair tables for this lane's pair index (lane>>2): 4 bits/round.
    int pr = lane >> 2;
    ull pT = 0, qT = 0;
    for (int rnd = 0; rnd < 15; rnd++) {
        int p = (pr == 0) ? 0 : ((pr - 1 + rnd) % 15) + 1;
        int q = ((14 - pr + rnd) % 15) + 1;
        pT |= ((ull)p) << (4 * rnd);
        qT |= ((ull)q) << (4 * rnd);
    }
    __syncwarp();

    initRow<false>(s, peps, 0, lane);
    for (int i = 1; i <= 4; i++) compress<false>(s, peps, i, lane, pT, qT);
    // bottom compressed MPS -> registers
    float br[20];
    #pragma unroll
    for (int t = 0; t < 20; t++) br[t] = s->small[lane + 32 * t];
    __syncwarp();

    initRow<true>(s, peps, 9, lane);
    for (int i = 8; i >= 5; i--) compress<true>(s, peps, i, lane, pT, qT);

    // dump bottom MPS into the (dead) arena for the zip
    float* botS = s->A;
    #pragma unroll
    for (int t = 0; t < 20; t++) botS[lane + 32 * t] = br[t];
    __syncwarp();

    // ---- zip ----
    if (lane < 16) {
        int c = lane >> 2, e2 = lane & 3;
        float acc = 0.f;
        #pragma unroll
        for (int d = 0; d < 4; d++) acc += botS[c * 4 + d] * s->small[e2 * 4 + d];
        s->Eb[lane] = acc;
    }
    __syncwarp();
    for (int j = 1; j <= 8; j++) {
        if (lane < 16) {
            int c = lane >> 2, e2 = lane & 3;
            float acc = 0.f;
            #pragma unroll
            for (int a = 0; a < 4; a++)
                #pragma unroll
                for (int b = 0; b < 4; b++) {
                    float ev = s->Eb[a * 4 + b];
                    float dot = 0.f;
                    #pragma unroll
                    for (int d = 0; d < 4; d++)
                        dot += botS[j * 64 + (a * 4 + c) * 4 + d]
                             * s->small[j * 64 + (b * 4 + e2) * 4 + d];
                    acc += ev * dot;
                }
            s->Eb2[lane] = acc;
        }
        __syncwarp();
        if (lane < 16) s->Eb[lane] = s->Eb2[lane];
        __syncwarp();
    }
    float part = 0.f;
    if (lane < 16) {
        int a = lane >> 2, b = lane & 3;
        float dot = 0.f;
        #pragma unroll
        for (int d = 0; d < 4; d++)
            dot += botS[9 * 64 + a * 4 + d] * s->small[9 * 64 + b * 4 + d];
        part = s->Eb[a * 4 + b] * dot;
    }
    part = wsum(part);
    if (lane == 0) out[blk] = part * expf(s->logn);
}

extern "C" void kernel_launch(void* const* d_in, const int* in_sizes, int n_in,
                              void* d_out, int out_size) {
    const int* x;
    const float* peps;
    if (in_sizes[0] == 51200 && n_in >= 2) {
        peps = (const float*)d_in[0];
        x = (const int*)d_in[1];
    } else {
        x = (const int*)d_in[0];
        peps = (const float*)d_in[1];
    }
    float* out = (float*)d_out;
    cudaFuncSetAttribute(amp_kernel, cudaFuncAttributeMaxDynamicSharedMemorySize, (int)sizeof(SM));
    amp_kernel<<<out_size, 32, sizeof(SM)>>>(x, peps, out);
}